// round 1
// baseline (speedup 1.0000x reference)
#include <cuda_runtime.h>
#include <math.h>

#define NPTS 65536
#define Hh 176
#define Ww 176
#define Dd 132
#define FD 32
#define LATD 128
#define OUTD 257
#define GATHER_BLOCKS 8192

// -------- scratch (static device globals: no allocation) --------
__device__ float g_bias[NPTS * LATD];     // unscaled bias_pre
__device__ float g_actA[NPTS * LATD];     // activation ping
__device__ float g_actB[NPTS * LATD];     // activation pong
__device__ float g_partial[GATHER_BLOCKS];
__device__ float g_scale;                 // (N*128)/sum(|bias_pre|)

// -------- helpers --------
__device__ __forceinline__ float sp100(float x) {
    // torch Softplus(beta=100, threshold=20)
    return (x > 0.2f) ? x : (log1pf(expf(x * 100.0f)) * 0.01f);
}

__device__ __forceinline__ unsigned long long pack2(float lo, float hi) {
    unsigned long long r;
    asm("mov.b64 %0, {%1, %2};" : "=l"(r) : "f"(lo), "f"(hi));
    return r;
}
__device__ __forceinline__ void unpack2(unsigned long long v, float& lo, float& hi) {
    asm("mov.b64 {%0, %1}, %2;" : "=f"(lo), "=f"(hi) : "l"(v));
}
// packed fp32x2 FMA: d = a*b + d  (Blackwell-only, 2x fp32 throughput)
__device__ __forceinline__ void ffma2(unsigned long long& d, unsigned long long a, unsigned long long b) {
    asm("fma.rn.f32x2 %0, %1, %2, %3;" : "=l"(d) : "l"(a), "l"(b), "l"(d));
}

// ======================================================================
// Kernel 1: gather + sim-weighted mix + Wq projection + per-block |.| sum
// One warp per point; lane = feature index (FD==32).
// feat_f = acc_f / sum_f(acc_f)   (sim-sum normalization cancels)
// ======================================================================
__global__ void __launch_bounds__(256) k_gather(
    const float* __restrict__ pixel, const float* __restrict__ vol,
    const float* __restrict__ Wq, const float* __restrict__ bq)
{
    const int warp_g = (blockIdx.x * blockDim.x + threadIdx.x) >> 5;  // point id
    const int lane = threadIdx.x & 31;

    // query coords — EXACT reference op order (floor boundary sensitivity)
    const float qx = pixel[warp_g * 3 + 0] + 24.0f;
    const float qy = pixel[warp_g * 3 + 1] + 24.0f;
    const float qz = ((pixel[warp_g * 3 + 2] - 425.0f) / 480.0f) * 128.0f;
    const int bx = (int)floorf(qx);
    const int by = (int)floorf(qy);
    const int bz = (int)floorf(qz);

    float acc = 0.0f;
#pragma unroll 4
    for (int k = 0; k < 64; k++) {
        const int ix = bx + (k >> 4) - 1;
        const int iy = by + ((k >> 2) & 3) - 1;
        const int iz = bz + (k & 3) - 1;
        const float sim = (float)ix * qx + (float)iy * qy + (float)iz * qz;
        const int addr = (((ix * Ww) + iy) * Dd + iz) * FD + lane;
        acc += sim * __ldg(vol + addr);
    }

    // sum over features (butterfly — deterministic)
    float tot = acc;
#pragma unroll
    for (int o = 16; o; o >>= 1) tot += __shfl_xor_sync(0xffffffffu, tot, o);
    const float feat = acc / tot;

    // bias_pre rows: each lane computes 4 rows (lane, lane+32, lane+64, lane+96)
    float r0 = bq[lane], r1 = bq[lane + 32], r2 = bq[lane + 64], r3 = bq[lane + 96];
#pragma unroll 8
    for (int f = 0; f < 32; f++) {
        const float xf = __shfl_sync(0xffffffffu, feat, f);
        r0 += Wq[(lane      ) * 32 + f] * xf;
        r1 += Wq[(lane + 32 ) * 32 + f] * xf;
        r2 += Wq[(lane + 64 ) * 32 + f] * xf;
        r3 += Wq[(lane + 96 ) * 32 + f] * xf;
    }
    float* bp = g_bias + (size_t)warp_g * LATD;
    bp[lane]      = r0;
    bp[lane + 32] = r1;
    bp[lane + 64] = r2;
    bp[lane + 96] = r3;

    // per-warp abs-sum, then per-block partial (deterministic tree)
    float s = fabsf(r0) + fabsf(r1) + fabsf(r2) + fabsf(r3);
#pragma unroll
    for (int o = 16; o; o >>= 1) s += __shfl_xor_sync(0xffffffffu, s, o);

    __shared__ float sred[8];
    const int wib = threadIdx.x >> 5;
    if (lane == 0) sred[wib] = s;
    __syncthreads();
    if (threadIdx.x == 0) {
        float t = 0.0f;
        for (int i = 0; i < 8; i++) t += sred[i];
        g_partial[blockIdx.x] = t;
    }
}

// ======================================================================
// Kernel 2: reduce partials -> g_scale  (deterministic)
// ======================================================================
__global__ void k_reduce() {
    __shared__ float sm[256];
    float s = 0.0f;
    for (int i = threadIdx.x; i < GATHER_BLOCKS; i += 256) s += g_partial[i];
    sm[threadIdx.x] = s;
    __syncthreads();
    for (int o = 128; o; o >>= 1) {
        if (threadIdx.x < o) sm[threadIdx.x] += sm[threadIdx.x + o];
        __syncthreads();
    }
    if (threadIdx.x == 0) g_scale = ((float)NPTS * (float)LATD) / sm[0];
}

// ======================================================================
// Kernel 3: layer 0 (3 -> 128), multiply by scaled bias, softplus
// ======================================================================
__global__ void __launch_bounds__(256) k_layer0(
    const float* __restrict__ world, const float* __restrict__ W0,
    const float* __restrict__ b0)
{
    const int gid = blockIdx.x * blockDim.x + threadIdx.x;
    const int m = gid >> 7, n = gid & 127;
    const float x0 = world[m * 3 + 0];
    const float x1 = world[m * 3 + 1];
    const float x2 = world[m * 3 + 2];
    float h = b0[n] + W0[n * 3 + 0] * x0 + W0[n * 3 + 1] * x1 + W0[n * 3 + 2] * x2;
    h *= g_bias[gid] * g_scale;
    g_actA[gid] = sp100(h);
}

// ======================================================================
// Kernel 4: mid layer GEMM (128 -> 128), fused bias/skip-concat/softplus
// BM=128 points/block, 512 threads, micro-tile 8m x 4n via f32x2 packed FMA.
// smem: xsT[128k][128m] (64KB) + W chunk wT[64k][128n] (32KB) = 96KB -> 2 blk/SM
// ======================================================================
__global__ void __launch_bounds__(512) k_mid(
    const float* __restrict__ Xin, const float* __restrict__ W,
    const float* __restrict__ b, float* __restrict__ Xout,
    int nvalid, const float* __restrict__ world)
{
    extern __shared__ float smd[];
    float* xsT = smd;           // [128][128] k-major
    float* wT  = smd + 16384;   // [64][128]  k-major chunk

    const int tid = threadIdx.x;
    const int m0 = blockIdx.x * 128;

    // load X tile transposed (warp reads one m-row contiguously)
    for (int i = tid; i < 128 * 32; i += 512) {
        const int m = i >> 5;
        const int k4 = (i & 31) * 4;
        const float4 xv = *reinterpret_cast<const float4*>(Xin + (size_t)(m0 + m) * LATD + k4);
        xsT[(k4 + 0) * 128 + m] = xv.x;
        xsT[(k4 + 1) * 128 + m] = xv.y;
        xsT[(k4 + 2) * 128 + m] = xv.z;
        xsT[(k4 + 3) * 128 + m] = xv.w;
    }

    const int ng = tid & 31;
    const int mg = tid >> 5;
    const int n0 = ng * 4;
    const int mm = mg * 8;

    unsigned long long acc[4][4];
#pragma unroll
    for (int i = 0; i < 4; i++)
#pragma unroll
        for (int j = 0; j < 4; j++) acc[i][j] = 0ull;

    for (int c = 0; c < 2; c++) {
        __syncthreads();
        // load W k-chunk transposed; rows >= nvalid are zero
        for (int i = tid; i < 128 * 16; i += 512) {
            const int n = i >> 4;
            const int k4 = (i & 15) * 4;
            float4 wv;
            if (n < nvalid) wv = *reinterpret_cast<const float4*>(W + (size_t)n * LATD + c * 64 + k4);
            else            wv = make_float4(0.f, 0.f, 0.f, 0.f);
            wT[(k4 + 0) * 128 + n] = wv.x;
            wT[(k4 + 1) * 128 + n] = wv.y;
            wT[(k4 + 2) * 128 + n] = wv.z;
            wT[(k4 + 3) * 128 + n] = wv.w;
        }
        __syncthreads();

#pragma unroll 2
        for (int kk = 0; kk < 64; kk++) {
            const unsigned long long* xp =
                reinterpret_cast<const unsigned long long*>(xsT + (c * 64 + kk) * 128 + mm);
            const unsigned long long xr0 = xp[0];
            const unsigned long long xr1 = xp[1];
            const unsigned long long xr2 = xp[2];
            const unsigned long long xr3 = xp[3];
            const float4 wv = *reinterpret_cast<const float4*>(wT + kk * 128 + n0);
            const unsigned long long w0 = pack2(wv.x, wv.x);
            const unsigned long long w1 = pack2(wv.y, wv.y);
            const unsigned long long w2 = pack2(wv.z, wv.z);
            const unsigned long long w3 = pack2(wv.w, wv.w);
            ffma2(acc[0][0], xr0, w0); ffma2(acc[0][1], xr0, w1);
            ffma2(acc[0][2], xr0, w2); ffma2(acc[0][3], xr0, w3);
            ffma2(acc[1][0], xr1, w0); ffma2(acc[1][1], xr1, w1);
            ffma2(acc[1][2], xr1, w2); ffma2(acc[1][3], xr1, w3);
            ffma2(acc[2][0], xr2, w0); ffma2(acc[2][1], xr2, w1);
            ffma2(acc[2][2], xr2, w2); ffma2(acc[2][3], xr2, w3);
            ffma2(acc[3][0], xr3, w0); ffma2(acc[3][1], xr3, w1);
            ffma2(acc[3][2], xr3, w2); ffma2(acc[3][3], xr3, w3);
        }
    }

    // epilogue: +bias, (skip: replace n>=125 with world coords), softplus, store
    float bv[4];
#pragma unroll
    for (int j = 0; j < 4; j++) {
        const int n = n0 + j;
        bv[j] = (n < nvalid) ? b[n] : 0.f;
    }
    const bool is_skip = (nvalid == 125);

#pragma unroll
    for (int i = 0; i < 4; i++) {
        float lo[4], hi[4];
#pragma unroll
        for (int j = 0; j < 4; j++) unpack2(acc[i][j], lo[j], hi[j]);
        const int mA = m0 + mm + 2 * i;
        const int mB = mA + 1;
        float oa[4], ob[4];
#pragma unroll
        for (int j = 0; j < 4; j++) {
            const int n = n0 + j;
            float ya = lo[j] + bv[j];
            float yb = hi[j] + bv[j];
            if (is_skip && n >= 125) {
                ya = world[(size_t)mA * 3 + (n - 125)];
                yb = world[(size_t)mB * 3 + (n - 125)];
            }
            oa[j] = sp100(ya);
            ob[j] = sp100(yb);
        }
        *reinterpret_cast<float4*>(Xout + (size_t)mA * LATD + n0) =
            make_float4(oa[0], oa[1], oa[2], oa[3]);
        *reinterpret_cast<float4*>(Xout + (size_t)mB * LATD + n0) =
            make_float4(ob[0], ob[1], ob[2], ob[3]);
    }
}

// ======================================================================
// Kernel 5: final layer GEMM (128 -> 257), no activation, writes d_out
// BN=64 chunks over blockIdx.y (5 chunks cover 257). micro-tile 8m x 2n.
// ======================================================================
__global__ void __launch_bounds__(512) k_last(
    const float* __restrict__ Xin, const float* __restrict__ W,
    const float* __restrict__ bvec, float* __restrict__ out)
{
    extern __shared__ float smd[];
    float* xsT = smd;           // [128][128]
    float* wT  = smd + 16384;   // [128][64]

    const int tid = threadIdx.x;
    const int m0 = blockIdx.x * 128;
    const int nbase = blockIdx.y * 64;

    for (int i = tid; i < 128 * 32; i += 512) {
        const int m = i >> 5;
        const int k4 = (i & 31) * 4;
        const float4 xv = *reinterpret_cast<const float4*>(Xin + (size_t)(m0 + m) * LATD + k4);
        xsT[(k4 + 0) * 128 + m] = xv.x;
        xsT[(k4 + 1) * 128 + m] = xv.y;
        xsT[(k4 + 2) * 128 + m] = xv.z;
        xsT[(k4 + 3) * 128 + m] = xv.w;
    }
    for (int i = tid; i < 64 * 32; i += 512) {
        const int nl = i >> 5;
        const int k4 = (i & 31) * 4;
        const int n = nbase + nl;
        float4 wv;
        if (n < OUTD) wv = *reinterpret_cast<const float4*>(W + (size_t)n * LATD + k4);
        else          wv = make_float4(0.f, 0.f, 0.f, 0.f);
        wT[(k4 + 0) * 64 + nl] = wv.x;
        wT[(k4 + 1) * 64 + nl] = wv.y;
        wT[(k4 + 2) * 64 + nl] = wv.z;
        wT[(k4 + 3) * 64 + nl] = wv.w;
    }
    __syncthreads();

    const int ng = tid & 31;
    const int mg = tid >> 5;
    const int n0 = ng * 2;
    const int mm = mg * 8;

    unsigned long long acc[4][2];
#pragma unroll
    for (int i = 0; i < 4; i++) { acc[i][0] = 0ull; acc[i][1] = 0ull; }

#pragma unroll 4
    for (int k = 0; k < 128; k++) {
        const unsigned long long* xp =
            reinterpret_cast<const unsigned long long*>(xsT + k * 128 + mm);
        const unsigned long long xr0 = xp[0];
        const unsigned long long xr1 = xp[1];
        const unsigned long long xr2 = xp[2];
        const unsigned long long xr3 = xp[3];
        const float2 wv = *reinterpret_cast<const float2*>(wT + k * 64 + n0);
        const unsigned long long w0 = pack2(wv.x, wv.x);
        const unsigned long long w1 = pack2(wv.y, wv.y);
        ffma2(acc[0][0], xr0, w0); ffma2(acc[0][1], xr0, w1);
        ffma2(acc[1][0], xr1, w0); ffma2(acc[1][1], xr1, w1);
        ffma2(acc[2][0], xr2, w0); ffma2(acc[2][1], xr2, w1);
        ffma2(acc[3][0], xr3, w0); ffma2(acc[3][1], xr3, w1);
    }

    float bj[2];
#pragma unroll
    for (int j = 0; j < 2; j++) {
        const int n = nbase + n0 + j;
        bj[j] = (n < OUTD) ? bvec[n] : 0.f;
    }
#pragma unroll
    for (int i = 0; i < 4; i++) {
        float lo[2], hi[2];
        unpack2(acc[i][0], lo[0], hi[0]);
        unpack2(acc[i][1], lo[1], hi[1]);
        const int mA = m0 + mm + 2 * i;
        const int mB = mA + 1;
#pragma unroll
        for (int j = 0; j < 2; j++) {
            const int n = nbase + n0 + j;
            if (n < OUTD) {
                out[(size_t)mA * OUTD + n] = lo[j] + bj[j];
                out[(size_t)mB * OUTD + n] = hi[j] + bj[j];
            }
        }
    }
}

// ======================================================================
extern "C" void kernel_launch(void* const* d_in, const int* in_sizes, int n_in,
                              void* d_out, int out_size)
{
    const float* world = (const float*)d_in[0];
    const float* pixel = (const float*)d_in[1];
    const float* vol   = (const float*)d_in[2];
    const float* Wq    = (const float*)d_in[3];
    const float* bq    = (const float*)d_in[4];
    const float* Wl[10];
    const float* bl[10];
    for (int l = 0; l < 10; l++) {
        Wl[l] = (const float*)d_in[5 + 2 * l];
        bl[l] = (const float*)d_in[6 + 2 * l];
    }
    float* out = (float*)d_out;

    cudaFuncSetAttribute(k_mid,  cudaFuncAttributeMaxDynamicSharedMemorySize, 98304);
    cudaFuncSetAttribute(k_last, cudaFuncAttributeMaxDynamicSharedMemorySize, 98304);

    float *pA = nullptr, *pB = nullptr;
    cudaGetSymbolAddress((void**)&pA, g_actA);
    cudaGetSymbolAddress((void**)&pB, g_actB);

    k_gather<<<GATHER_BLOCKS, 256>>>(pixel, vol, Wq, bq);
    k_reduce<<<1, 256>>>();
    k_layer0<<<NPTS * LATD / 256, 256>>>(world, Wl[0], bl[0]);

    const float* cur = pA;
    float* nxt = pB;
    for (int l = 1; l <= 8; l++) {
        const int nvalid = (l == 4) ? 125 : 128;
        k_mid<<<NPTS / 128, 512, 98304>>>(cur, Wl[l], bl[l], nxt, nvalid, world);
        float* t = nxt;
        nxt = (float*)cur;
        cur = t;
    }
    dim3 g9(NPTS / 128, 5);
    k_last<<<g9, 512, 98304>>>(cur, Wl[9], bl[9], out);
}

// round 2
// speedup vs baseline: 1.6421x; 1.6421x over previous
#include <cuda_runtime.h>
#include <math.h>

#define NPTS 65536
#define Hh 176
#define Ww 176
#define Dd 132
#define FD 32
#define LATD 128
#define OUTD 257
#define GATHER_BLOCKS 8192

// -------- scratch (static device globals: no allocation) --------
__device__ float g_bias[NPTS * LATD];     // unscaled bias_pre
__device__ float g_actA[NPTS * LATD];     // activation ping
__device__ float g_actB[NPTS * LATD];     // activation pong
__device__ float g_partial[GATHER_BLOCKS];
__device__ float g_scale;                 // (N*128)/sum(|bias_pre|)

// -------- helpers --------
__device__ __forceinline__ float sp100(float x) {
    // torch Softplus(beta=100, threshold=20)
    return (x > 0.2f) ? x : (log1pf(expf(x * 100.0f)) * 0.01f);
}

__device__ __forceinline__ unsigned long long pack2(float lo, float hi) {
    unsigned long long r;
    asm("mov.b64 %0, {%1, %2};" : "=l"(r) : "f"(lo), "f"(hi));
    return r;
}
__device__ __forceinline__ void unpack2(unsigned long long v, float& lo, float& hi) {
    asm("mov.b64 {%0, %1}, %2;" : "=f"(lo), "=f"(hi) : "l"(v));
}
// packed fp32x2 FMA: d = a*b + d  (Blackwell-only, 2x fp32 throughput)
__device__ __forceinline__ void ffma2(unsigned long long& d, unsigned long long a, unsigned long long b) {
    asm("fma.rn.f32x2 %0, %1, %2, %3;" : "=l"(d) : "l"(a), "l"(b), "l"(d));
}

// ======================================================================
// Kernel 1: gather + sim-weighted mix + Wq projection + per-block |.| sum
// One warp per point; lane = feature index (FD==32).
// feat_f = acc_f / sum_f(acc_f)   (sim-sum normalization cancels)
// ======================================================================
__global__ void __launch_bounds__(256) k_gather(
    const float* __restrict__ pixel, const float* __restrict__ vol,
    const float* __restrict__ Wq, const float* __restrict__ bq)
{
    const int warp_g = (blockIdx.x * blockDim.x + threadIdx.x) >> 5;  // point id
    const int lane = threadIdx.x & 31;

    // query coords — EXACT reference op order (floor boundary sensitivity)
    const float qx = pixel[warp_g * 3 + 0] + 24.0f;
    const float qy = pixel[warp_g * 3 + 1] + 24.0f;
    const float qz = ((pixel[warp_g * 3 + 2] - 425.0f) / 480.0f) * 128.0f;
    const int bx = (int)floorf(qx);
    const int by = (int)floorf(qy);
    const int bz = (int)floorf(qz);

    float acc = 0.0f;
#pragma unroll 4
    for (int k = 0; k < 64; k++) {
        const int ix = bx + (k >> 4) - 1;
        const int iy = by + ((k >> 2) & 3) - 1;
        const int iz = bz + (k & 3) - 1;
        const float sim = (float)ix * qx + (float)iy * qy + (float)iz * qz;
        const int addr = (((ix * Ww) + iy) * Dd + iz) * FD + lane;
        acc += sim * __ldg(vol + addr);
    }

    // sum over features (butterfly — deterministic)
    float tot = acc;
#pragma unroll
    for (int o = 16; o; o >>= 1) tot += __shfl_xor_sync(0xffffffffu, tot, o);
    const float feat = acc / tot;

    // bias_pre rows: each lane computes 4 rows (lane, lane+32, lane+64, lane+96)
    float r0 = bq[lane], r1 = bq[lane + 32], r2 = bq[lane + 64], r3 = bq[lane + 96];
#pragma unroll 8
    for (int f = 0; f < 32; f++) {
        const float xf = __shfl_sync(0xffffffffu, feat, f);
        r0 += Wq[(lane      ) * 32 + f] * xf;
        r1 += Wq[(lane + 32 ) * 32 + f] * xf;
        r2 += Wq[(lane + 64 ) * 32 + f] * xf;
        r3 += Wq[(lane + 96 ) * 32 + f] * xf;
    }
    float* bp = g_bias + (size_t)warp_g * LATD;
    bp[lane]      = r0;
    bp[lane + 32] = r1;
    bp[lane + 64] = r2;
    bp[lane + 96] = r3;

    // per-warp abs-sum, then per-block partial (deterministic tree)
    float s = fabsf(r0) + fabsf(r1) + fabsf(r2) + fabsf(r3);
#pragma unroll
    for (int o = 16; o; o >>= 1) s += __shfl_xor_sync(0xffffffffu, s, o);

    __shared__ float sred[8];
    const int wib = threadIdx.x >> 5;
    if (lane == 0) sred[wib] = s;
    __syncthreads();
    if (threadIdx.x == 0) {
        float t = 0.0f;
        for (int i = 0; i < 8; i++) t += sred[i];
        g_partial[blockIdx.x] = t;
    }
}

// ======================================================================
// Kernel 2: reduce partials -> g_scale  (deterministic)
// ======================================================================
__global__ void k_reduce() {
    __shared__ float sm[256];
    float s = 0.0f;
    for (int i = threadIdx.x; i < GATHER_BLOCKS; i += 256) s += g_partial[i];
    sm[threadIdx.x] = s;
    __syncthreads();
    for (int o = 128; o; o >>= 1) {
        if (threadIdx.x < o) sm[threadIdx.x] += sm[threadIdx.x + o];
        __syncthreads();
    }
    if (threadIdx.x == 0) g_scale = ((float)NPTS * (float)LATD) / sm[0];
}

// ======================================================================
// Kernel 3: layer 0 (3 -> 128), multiply by scaled bias, softplus
// ======================================================================
__global__ void __launch_bounds__(256) k_layer0(
    const float* __restrict__ world, const float* __restrict__ W0,
    const float* __restrict__ b0)
{
    const int gid = blockIdx.x * blockDim.x + threadIdx.x;
    const int m = gid >> 7, n = gid & 127;
    const float x0 = world[m * 3 + 0];
    const float x1 = world[m * 3 + 1];
    const float x2 = world[m * 3 + 2];
    float h = b0[n] + W0[n * 3 + 0] * x0 + W0[n * 3 + 1] * x1 + W0[n * 3 + 2] * x2;
    h *= g_bias[gid] * g_scale;
    g_actA[gid] = sp100(h);
}

// ======================================================================
// Kernel 4: mid layer GEMM (128 -> 128), fused bias/skip-concat/softplus
// BM=128 points/block, 512 threads, micro-tile 8m x 4n via f32x2 packed FMA.
// smem: xsT[128k][128m] (64KB) + W chunk wT[64k][128n] (32KB) = 96KB -> 2 blk/SM
// ======================================================================
__global__ void __launch_bounds__(512) k_mid(
    const float* __restrict__ Xin, const float* __restrict__ W,
    const float* __restrict__ b, float* __restrict__ Xout,
    int nvalid, const float* __restrict__ world)
{
    extern __shared__ float smd[];
    float* xsT = smd;           // [128][128] k-major
    float* wT  = smd + 16384;   // [64][128]  k-major chunk

    const int tid = threadIdx.x;
    const int m0 = blockIdx.x * 128;

    // load X tile transposed (warp reads one m-row contiguously)
    for (int i = tid; i < 128 * 32; i += 512) {
        const int m = i >> 5;
        const int k4 = (i & 31) * 4;
        const float4 xv = *reinterpret_cast<const float4*>(Xin + (size_t)(m0 + m) * LATD + k4);
        xsT[(k4 + 0) * 128 + m] = xv.x;
        xsT[(k4 + 1) * 128 + m] = xv.y;
        xsT[(k4 + 2) * 128 + m] = xv.z;
        xsT[(k4 + 3) * 128 + m] = xv.w;
    }

    const int ng = tid & 31;
    const int mg = tid >> 5;
    const int n0 = ng * 4;
    const int mm = mg * 8;

    unsigned long long acc[4][4];
#pragma unroll
    for (int i = 0; i < 4; i++)
#pragma unroll
        for (int j = 0; j < 4; j++) acc[i][j] = 0ull;

    for (int c = 0; c < 2; c++) {
        __syncthreads();
        // load W k-chunk transposed; rows >= nvalid are zero
        for (int i = tid; i < 128 * 16; i += 512) {
            const int n = i >> 4;
            const int k4 = (i & 15) * 4;
            float4 wv;
            if (n < nvalid) wv = *reinterpret_cast<const float4*>(W + (size_t)n * LATD + c * 64 + k4);
            else            wv = make_float4(0.f, 0.f, 0.f, 0.f);
            wT[(k4 + 0) * 128 + n] = wv.x;
            wT[(k4 + 1) * 128 + n] = wv.y;
            wT[(k4 + 2) * 128 + n] = wv.z;
            wT[(k4 + 3) * 128 + n] = wv.w;
        }
        __syncthreads();

#pragma unroll 2
        for (int kk = 0; kk < 64; kk++) {
            const unsigned long long* xp =
                reinterpret_cast<const unsigned long long*>(xsT + (c * 64 + kk) * 128 + mm);
            const unsigned long long xr0 = xp[0];
            const unsigned long long xr1 = xp[1];
            const unsigned long long xr2 = xp[2];
            const unsigned long long xr3 = xp[3];
            const float4 wv = *reinterpret_cast<const float4*>(wT + kk * 128 + n0);
            const unsigned long long w0 = pack2(wv.x, wv.x);
            const unsigned long long w1 = pack2(wv.y, wv.y);
            const unsigned long long w2 = pack2(wv.z, wv.z);
            const unsigned long long w3 = pack2(wv.w, wv.w);
            ffma2(acc[0][0], xr0, w0); ffma2(acc[0][1], xr0, w1);
            ffma2(acc[0][2], xr0, w2); ffma2(acc[0][3], xr0, w3);
            ffma2(acc[1][0], xr1, w0); ffma2(acc[1][1], xr1, w1);
            ffma2(acc[1][2], xr1, w2); ffma2(acc[1][3], xr1, w3);
            ffma2(acc[2][0], xr2, w0); ffma2(acc[2][1], xr2, w1);
            ffma2(acc[2][2], xr2, w2); ffma2(acc[2][3], xr2, w3);
            ffma2(acc[3][0], xr3, w0); ffma2(acc[3][1], xr3, w1);
            ffma2(acc[3][2], xr3, w2); ffma2(acc[3][3], xr3, w3);
        }
    }

    // epilogue: +bias, (skip: replace n>=125 with world coords), softplus, store
    float bv[4];
#pragma unroll
    for (int j = 0; j < 4; j++) {
        const int n = n0 + j;
        bv[j] = (n < nvalid) ? b[n] : 0.f;
    }
    const bool is_skip = (nvalid == 125);

#pragma unroll
    for (int i = 0; i < 4; i++) {
        float lo[4], hi[4];
#pragma unroll
        for (int j = 0; j < 4; j++) unpack2(acc[i][j], lo[j], hi[j]);
        const int mA = m0 + mm + 2 * i;
        const int mB = mA + 1;
        float oa[4], ob[4];
#pragma unroll
        for (int j = 0; j < 4; j++) {
            const int n = n0 + j;
            float ya = lo[j] + bv[j];
            float yb = hi[j] + bv[j];
            if (is_skip && n >= 125) {
                ya = world[(size_t)mA * 3 + (n - 125)];
                yb = world[(size_t)mB * 3 + (n - 125)];
            }
            oa[j] = sp100(ya);
            ob[j] = sp100(yb);
        }
        *reinterpret_cast<float4*>(Xout + (size_t)mA * LATD + n0) =
            make_float4(oa[0], oa[1], oa[2], oa[3]);
        *reinterpret_cast<float4*>(Xout + (size_t)mB * LATD + n0) =
            make_float4(ob[0], ob[1], ob[2], ob[3]);
    }
}

// ======================================================================
// Kernel 5: final layer GEMM (128 -> 257), no activation, writes d_out
// BN=64 chunks over blockIdx.y (5 chunks cover 257). micro-tile 8m x 2n.
// ======================================================================
__global__ void __launch_bounds__(512) k_last(
    const float* __restrict__ Xin, const float* __restrict__ W,
    const float* __restrict__ bvec, float* __restrict__ out)
{
    extern __shared__ float smd[];
    float* xsT = smd;           // [128][128]
    float* wT  = smd + 16384;   // [128][64]

    const int tid = threadIdx.x;
    const int m0 = blockIdx.x * 128;
    const int nbase = blockIdx.y * 64;

    for (int i = tid; i < 128 * 32; i += 512) {
        const int m = i >> 5;
        const int k4 = (i & 31) * 4;
        const float4 xv = *reinterpret_cast<const float4*>(Xin + (size_t)(m0 + m) * LATD + k4);
        xsT[(k4 + 0) * 128 + m] = xv.x;
        xsT[(k4 + 1) * 128 + m] = xv.y;
        xsT[(k4 + 2) * 128 + m] = xv.z;
        xsT[(k4 + 3) * 128 + m] = xv.w;
    }
    for (int i = tid; i < 64 * 32; i += 512) {
        const int nl = i >> 5;
        const int k4 = (i & 31) * 4;
        const int n = nbase + nl;
        float4 wv;
        if (n < OUTD) wv = *reinterpret_cast<const float4*>(W + (size_t)n * LATD + k4);
        else          wv = make_float4(0.f, 0.f, 0.f, 0.f);
        wT[(k4 + 0) * 64 + nl] = wv.x;
        wT[(k4 + 1) * 64 + nl] = wv.y;
        wT[(k4 + 2) * 64 + nl] = wv.z;
        wT[(k4 + 3) * 64 + nl] = wv.w;
    }
    __syncthreads();

    const int ng = tid & 31;
    const int mg = tid >> 5;
    const int n0 = ng * 2;
    const int mm = mg * 8;

    unsigned long long acc[4][2];
#pragma unroll
    for (int i = 0; i < 4; i++) { acc[i][0] = 0ull; acc[i][1] = 0ull; }

#pragma unroll 4
    for (int k = 0; k < 128; k++) {
        const unsigned long long* xp =
            reinterpret_cast<const unsigned long long*>(xsT + k * 128 + mm);
        const unsigned long long xr0 = xp[0];
        const unsigned long long xr1 = xp[1];
        const unsigned long long xr2 = xp[2];
        const unsigned long long xr3 = xp[3];
        const float2 wv = *reinterpret_cast<const float2*>(wT + k * 64 + n0);
        const unsigned long long w0 = pack2(wv.x, wv.x);
        const unsigned long long w1 = pack2(wv.y, wv.y);
        ffma2(acc[0][0], xr0, w0); ffma2(acc[0][1], xr0, w1);
        ffma2(acc[1][0], xr1, w0); ffma2(acc[1][1], xr1, w1);
        ffma2(acc[2][0], xr2, w0); ffma2(acc[2][1], xr2, w1);
        ffma2(acc[3][0], xr3, w0); ffma2(acc[3][1], xr3, w1);
    }

    float bj[2];
#pragma unroll
    for (int j = 0; j < 2; j++) {
        const int n = nbase + n0 + j;
        bj[j] = (n < OUTD) ? bvec[n] : 0.f;
    }
#pragma unroll
    for (int i = 0; i < 4; i++) {
        float lo[2], hi[2];
        unpack2(acc[i][0], lo[0], hi[0]);
        unpack2(acc[i][1], lo[1], hi[1]);
        const int mA = m0 + mm + 2 * i;
        const int mB = mA + 1;
#pragma unroll
        for (int j = 0; j < 2; j++) {
            const int n = nbase + n0 + j;
            if (n < OUTD) {
                out[(size_t)mA * OUTD + n] = lo[j] + bj[j];
                out[(size_t)mB * OUTD + n] = hi[j] + bj[j];
            }
        }
    }
}

// ======================================================================
extern "C" void kernel_launch(void* const* d_in, const int* in_sizes, int n_in,
                              void* d_out, int out_size)
{
    const float* world = (const float*)d_in[0];
    const float* pixel = (const float*)d_in[1];
    const float* vol   = (const float*)d_in[2];
    const float* Wq    = (const float*)d_in[3];
    const float* bq    = (const float*)d_in[4];
    const float* Wl[10];
    const float* bl[10];
    for (int l = 0; l < 10; l++) {
        Wl[l] = (const float*)d_in[5 + 2 * l];
        bl[l] = (const float*)d_in[6 + 2 * l];
    }
    float* out = (float*)d_out;

    cudaFuncSetAttribute(k_mid,  cudaFuncAttributeMaxDynamicSharedMemorySize, 98304);
    cudaFuncSetAttribute(k_last, cudaFuncAttributeMaxDynamicSharedMemorySize, 98304);

    float *pA = nullptr, *pB = nullptr;
    cudaGetSymbolAddress((void**)&pA, g_actA);
    cudaGetSymbolAddress((void**)&pB, g_actB);

    k_gather<<<GATHER_BLOCKS, 256>>>(pixel, vol, Wq, bq);
    k_reduce<<<1, 256>>>();
    k_layer0<<<NPTS * LATD / 256, 256>>>(world, Wl[0], bl[0]);

    const float* cur = pA;
    float* nxt = pB;
    for (int l = 1; l <= 8; l++) {
        const int nvalid = (l == 4) ? 125 : 128;
        k_mid<<<NPTS / 128, 512, 98304>>>(cur, Wl[l], bl[l], nxt, nvalid, world);
        float* t = nxt;
        nxt = (float*)cur;
        cur = t;
    }
    dim3 g9(NPTS / 128, 5);
    k_last<<<g9, 512, 98304>>>(cur, Wl[9], bl[9], out);
}

// round 7
// speedup vs baseline: 4.6115x; 2.8083x over previous
#include <cuda_runtime.h>
#include <cuda_bf16.h>
#include <math.h>
#include <stdint.h>

#define NPTS 65536
#define Wdim 176
#define Ddim 132
#define LATD 128
#define OUTD 257
#define GB 8192

__device__ float g_bias[NPTS * LATD];
__device__ float g_actA[NPTS * LATD];
__device__ float g_actB[NPTS * LATD];
__device__ float g_partial[GB];
__device__ float g_scale;

// ---------------- helpers ----------------
__device__ __forceinline__ float sp100(float x) {
    return (x > 0.2f) ? x : (log1pf(expf(x * 100.0f)) * 0.01f);
}
__device__ __forceinline__ uint32_t smem_u32(const void* p) {
    uint32_t a;
    asm("{ .reg .u64 t; cvta.to.shared.u64 t, %1; cvt.u32.u64 %0, t; }" : "=r"(a) : "l"(p));
    return a;
}
// swizzled byte offset in a bf16 tile with 256B rows (128 cols):
// 16B chunk index kc XOR'd with (row&7) -> ldmatrix conflict-free
__device__ __forceinline__ uint32_t swz(int r, int cp) {  // cp = even col index
    const int kc = cp >> 3;
    return (uint32_t)(r * 256 + (((kc ^ (r & 7)) << 4) | ((cp * 2) & 15)));
}
__device__ __forceinline__ void split2(float a, float b, uint32_t& hi, uint32_t& lo) {
    __nv_bfloat16 ah = __float2bfloat16_rn(a), bh = __float2bfloat16_rn(b);
    __nv_bfloat16 al = __float2bfloat16_rn(a - __bfloat162float(ah));
    __nv_bfloat16 bl = __float2bfloat16_rn(b - __bfloat162float(bh));
    hi = (uint32_t)__bfloat16_as_ushort(ah) | ((uint32_t)__bfloat16_as_ushort(bh) << 16);
    lo = (uint32_t)__bfloat16_as_ushort(al) | ((uint32_t)__bfloat16_as_ushort(bl) << 16);
}
#define LDSM_X4(r, a) asm volatile( \
    "ldmatrix.sync.aligned.m8n8.x4.shared.b16 {%0,%1,%2,%3}, [%4];" \
    : "=r"((r)[0]), "=r"((r)[1]), "=r"((r)[2]), "=r"((r)[3]) : "r"(a))
#define LDSM_X2(r0, r1, a) asm volatile( \
    "ldmatrix.sync.aligned.m8n8.x2.shared.b16 {%0,%1}, [%2];" \
    : "=r"(r0), "=r"(r1) : "r"(a))
#define MMA(c, a, b0, b1) asm volatile( \
    "mma.sync.aligned.m16n8k16.row.col.f32.bf16.bf16.f32 " \
    "{%0,%1,%2,%3}, {%4,%5,%6,%7}, {%8,%9}, {%0,%1,%2,%3};" \
    : "+f"((c)[0]), "+f"((c)[1]), "+f"((c)[2]), "+f"((c)[3]) \
    : "r"((a)[0]), "r"((a)[1]), "r"((a)[2]), "r"((a)[3]), "r"(b0), "r"(b1))

// ============ k_gather: volume mix + Wq projection (Wq^T staged in smem) ============
__global__ void __launch_bounds__(256) k_gather(
    const float* __restrict__ pixel, const float* __restrict__ vol,
    const float* __restrict__ Wq, const float* __restrict__ bq)
{
    __shared__ float sWqT[32 * 129];
    __shared__ float sred[8];
    const int tid = threadIdx.x;
    for (int i = tid; i < 4096; i += 256) sWqT[(i & 31) * 129 + (i >> 5)] = Wq[i];
    __syncthreads();

    const int warp_g = (blockIdx.x * 256 + tid) >> 5;
    const int lane = tid & 31;
    const float qx = pixel[warp_g * 3 + 0] + 24.0f;
    const float qy = pixel[warp_g * 3 + 1] + 24.0f;
    const float qz = ((pixel[warp_g * 3 + 2] - 425.0f) / 480.0f) * 128.0f;
    const int bx = (int)floorf(qx), by = (int)floorf(qy), bz = (int)floorf(qz);

    float acc = 0.0f;
#pragma unroll 8
    for (int k = 0; k < 64; k++) {
        const int ix = bx + (k >> 4) - 1;
        const int iy = by + ((k >> 2) & 3) - 1;
        const int iz = bz + (k & 3) - 1;
        const float sim = (float)ix * qx + (float)iy * qy + (float)iz * qz;
        acc += sim * __ldg(vol + (((ix * Wdim) + iy) * Ddim + iz) * 32 + lane);
    }
    float tot = acc;
#pragma unroll
    for (int o = 16; o; o >>= 1) tot += __shfl_xor_sync(0xffffffffu, tot, o);
    const float feat = acc / tot;

    float r0 = bq[lane], r1 = bq[lane + 32], r2 = bq[lane + 64], r3 = bq[lane + 96];
#pragma unroll 8
    for (int f = 0; f < 32; f++) {
        const float xf = __shfl_sync(0xffffffffu, feat, f);
        const float* wr = sWqT + f * 129 + lane;
        r0 += wr[0] * xf; r1 += wr[32] * xf; r2 += wr[64] * xf; r3 += wr[96] * xf;
    }
    float* bp = g_bias + (size_t)warp_g * LATD;
    bp[lane] = r0; bp[lane + 32] = r1; bp[lane + 64] = r2; bp[lane + 96] = r3;

    float s = fabsf(r0) + fabsf(r1) + fabsf(r2) + fabsf(r3);
#pragma unroll
    for (int o = 16; o; o >>= 1) s += __shfl_xor_sync(0xffffffffu, s, o);
    if (lane == 0) sred[tid >> 5] = s;
    __syncthreads();
    if (tid == 0) {
        float t = 0.0f;
        for (int i = 0; i < 8; i++) t += sred[i];
        g_partial[blockIdx.x] = t;
    }
}

__global__ void k_reduce() {
    __shared__ float sm[256];
    float s = 0.0f;
    for (int i = threadIdx.x; i < GB; i += 256) s += g_partial[i];
    sm[threadIdx.x] = s;
    __syncthreads();
    for (int o = 128; o; o >>= 1) {
        if (threadIdx.x < o) sm[threadIdx.x] += sm[threadIdx.x + o];
        __syncthreads();
    }
    if (threadIdx.x == 0) g_scale = ((float)NPTS * (float)LATD) / sm[0];
}

__global__ void __launch_bounds__(256) k_layer0(
    const float* __restrict__ world, const float* __restrict__ W0, const float* __restrict__ b0)
{
    const int gid = blockIdx.x * 256 + threadIdx.x;
    const int m = gid >> 7, n = gid & 127;
    float h = b0[n] + W0[n * 3] * world[m * 3] + W0[n * 3 + 1] * world[m * 3 + 1] +
              W0[n * 3 + 2] * world[m * 3 + 2];
    h *= g_bias[gid] * g_scale;
    g_actA[gid] = sp100(h);
}

// ============ k_mid: 128->128 layer via mma.sync bf16 hi/lo split ============
// smem: XH 0 | XL 32768 | WH 65536 | WL 98304   (131072 B)
__global__ void __launch_bounds__(512, 1) k_mid(
    const float* __restrict__ Xin, const float* __restrict__ W, const float* __restrict__ b,
    float* __restrict__ Xout, int nvalid, const float* __restrict__ world)
{
    extern __shared__ uint8_t sm[];
    const int tid = threadIdx.x, w = tid >> 5, T = tid & 31;
    const int m0 = blockIdx.x * 128;
    const uint32_t sb = smem_u32(sm);

    for (int i = tid; i < 8192; i += 512) {
        const int m = i >> 6, cp = (i & 63) * 2;
        const float2 xv = *(const float2*)(Xin + (size_t)(m0 + m) * LATD + cp);
        uint32_t hi, lo;
        split2(xv.x, xv.y, hi, lo);
        const uint32_t o = swz(m, cp);
        *(uint32_t*)(sm + o) = hi;
        *(uint32_t*)(sm + 32768 + o) = lo;
        float2 wv = make_float2(0.f, 0.f);
        if (m < nvalid) wv = *(const float2*)(W + (size_t)m * LATD + cp);
        split2(wv.x, wv.y, hi, lo);
        *(uint32_t*)(sm + 65536 + o) = hi;
        *(uint32_t*)(sm + 98304 + o) = lo;
    }
    __syncthreads();

    const int mb = (w & 7) * 16, nh = w >> 3;
    const int arow = mb + (T & 7) + ((T >> 3) & 1) * 8;
    const int akoff = (T >> 4) & 1;
    const int bkoff = (T >> 3) & 1;
    const int t7 = T & 7;

    float acc[8][4];
#pragma unroll
    for (int i = 0; i < 8; i++)
#pragma unroll
        for (int j = 0; j < 4; j++) acc[i][j] = 0.f;

#pragma unroll
    for (int ks = 0; ks < 8; ks++) {
        uint32_t ah[4], al[4];
        const uint32_t ao = (uint32_t)(arow * 256 + (((2 * ks + akoff) ^ (arow & 7)) << 4));
        LDSM_X4(ah, sb + ao);
        LDSM_X4(al, sb + 32768 + ao);
        const uint32_t bx = (uint32_t)((((2 * ks + bkoff) ^ t7) << 4) + t7 * 256);
#pragma unroll
        for (int nb = 0; nb < 8; nb++) {
            const uint32_t bo = bx + (uint32_t)((nh * 64 + nb * 8) * 256);
            uint32_t bh0, bh1, bl0, bl1;
            LDSM_X2(bh0, bh1, sb + 65536 + bo);
            LDSM_X2(bl0, bl1, sb + 98304 + bo);
            MMA(acc[nb], ah, bh0, bh1);
            MMA(acc[nb], ah, bl0, bl1);
            MMA(acc[nb], al, bh0, bh1);
        }
    }

    const int r1 = m0 + mb + (T >> 2), r2 = r1 + 8;
    const bool skl = (nvalid == 125);
#pragma unroll
    for (int nb = 0; nb < 8; nb++) {
        const int n = nh * 64 + nb * 8 + (T & 3) * 2;
        float y0 = acc[nb][0] + b[n], y1 = acc[nb][1] + b[n + 1];
        float y2 = acc[nb][2] + b[n], y3 = acc[nb][3] + b[n + 1];
        if (skl && n >= 125) {
            y0 = world[(size_t)r1 * 3 + (n - 125)];
            y2 = world[(size_t)r2 * 3 + (n - 125)];
        }
        if (skl && n + 1 >= 125) {
            y1 = world[(size_t)r1 * 3 + (n - 124)];
            y3 = world[(size_t)r2 * 3 + (n - 124)];
        }
        *(float2*)(Xout + (size_t)r1 * LATD + n) = make_float2(sp100(y0), sp100(y1));
        *(float2*)(Xout + (size_t)r2 * LATD + n) = make_float2(sp100(y2), sp100(y3));
    }
}

// ============ k_last: 128->257 (chunk0 N=128, chunk1 N=136 padded) ============
// smem: XH 0 | XL 32768 | WH 65536 (34816) | WL 100352 (34816)  = 135168 B
__global__ void __launch_bounds__(512, 1) k_last(
    const float* __restrict__ Xin, const float* __restrict__ W9, const float* __restrict__ b9,
    float* __restrict__ out)
{
    extern __shared__ uint8_t sm[];
    const int tid = threadIdx.x, w = tid >> 5, T = tid & 31;
    const int m0 = blockIdx.x * 128;
    const int chunk = blockIdx.y, nbase = chunk * 128;
    const int rowsP = chunk ? 136 : 128;
    const uint32_t sb = smem_u32(sm);

    for (int i = tid; i < 8192; i += 512) {
        const int m = i >> 6, cp = (i & 63) * 2;
        const float2 xv = *(const float2*)(Xin + (size_t)(m0 + m) * LATD + cp);
        uint32_t hi, lo;
        split2(xv.x, xv.y, hi, lo);
        const uint32_t o = swz(m, cp);
        *(uint32_t*)(sm + o) = hi;
        *(uint32_t*)(sm + 32768 + o) = lo;
    }
    for (int i = tid; i < rowsP * 64; i += 512) {
        const int rl = i >> 6, cp = (i & 63) * 2;
        const int n = nbase + rl;
        float2 wv = make_float2(0.f, 0.f);
        if (n < OUTD) wv = *(const float2*)(W9 + (size_t)n * LATD + cp);
        uint32_t hi, lo;
        split2(wv.x, wv.y, hi, lo);
        const uint32_t o = swz(rl, cp);
        *(uint32_t*)(sm + 65536 + o) = hi;
        *(uint32_t*)(sm + 100352 + o) = lo;
    }
    __syncthreads();

    const int mb = (w & 7) * 16, nh = w >> 3;
    const int nbcnt = chunk ? (nh ? 8 : 9) : 8;
    const int hbase = chunk ? nh * 72 : nh * 64;
    const int arow = mb + (T & 7) + ((T >> 3) & 1) * 8;
    const int akoff = (T >> 4) & 1;
    const int bkoff = (T >> 3) & 1;
    const int t7 = T & 7;

    float acc[9][4];
#pragma unroll
    for (int i = 0; i < 9; i++)
#pragma unroll
        for (int j = 0; j < 4; j++) acc[i][j] = 0.f;

#pragma unroll
    for (int ks = 0; ks < 8; ks++) {
        uint32_t ah[4], al[4];
        const uint32_t ao = (uint32_t)(arow * 256 + (((2 * ks + akoff) ^ (arow & 7)) << 4));
        LDSM_X4(ah, sb + ao);
        LDSM_X4(al, sb + 32768 + ao);
        const uint32_t bx = (uint32_t)((((2 * ks + bkoff) ^ t7) << 4) + t7 * 256);
        for (int nb = 0; nb < nbcnt; nb++) {
            const uint32_t bo = bx + (uint32_t)((hbase + nb * 8) * 256);
            uint32_t bh0, bh1, bl0, bl1;
            LDSM_X2(bh0, bh1, sb + 65536 + bo);
            LDSM_X2(bl0, bl1, sb + 100352 + bo);
            MMA(acc[nb], ah, bh0, bh1);
            MMA(acc[nb], ah, bl0, bl1);
            MMA(acc[nb], al, bh0, bh1);
        }
    }

    const int r1 = m0 + mb + (T >> 2), r2 = r1 + 8;
    for (int nb = 0; nb < nbcnt; nb++) {
        const int n = nbase + hbase + nb * 8 + (T & 3) * 2;
        if (n < OUTD) {
            out[(size_t)r1 * OUTD + n] = acc[nb][0] + b9[n];
            out[(size_t)r2 * OUTD + n] = acc[nb][2] + b9[n];
        }
        if (n + 1 < OUTD) {
            out[(size_t)r1 * OUTD + n + 1] = acc[nb][1] + b9[n + 1];
            out[(size_t)r2 * OUTD + n + 1] = acc[nb][3] + b9[n + 1];
        }
    }
}

// ======================================================================
extern "C" void kernel_launch(void* const* d_in, const int* in_sizes, int n_in,
                              void* d_out, int out_size)
{
    const float* world = (const float*)d_in[0];
    const float* pixel = (const float*)d_in[1];
    const float* vol   = (const float*)d_in[2];
    const float* Wq    = (const float*)d_in[3];
    const float* bq    = (const float*)d_in[4];
    const float* Wl[10];
    const float* bl[10];
    for (int l = 0; l < 10; l++) {
        Wl[l] = (const float*)d_in[5 + 2 * l];
        bl[l] = (const float*)d_in[6 + 2 * l];
    }
    float* out = (float*)d_out;

    cudaFuncSetAttribute(k_mid,  cudaFuncAttributeMaxDynamicSharedMemorySize, 131072);
    cudaFuncSetAttribute(k_last, cudaFuncAttributeMaxDynamicSharedMemorySize, 135168);

    float *pA = nullptr, *pB = nullptr;
    cudaGetSymbolAddress((void**)&pA, g_actA);
    cudaGetSymbolAddress((void**)&pB, g_actB);

    k_gather<<<GB, 256>>>(pixel, vol, Wq, bq);
    k_reduce<<<1, 256>>>();
    k_layer0<<<NPTS * LATD / 256, 256>>>(world, Wl[0], bl[0]);

    const float* cur = pA;
    float* nxt = pB;
    for (int l = 1; l <= 8; l++) {
        k_mid<<<NPTS / 128, 512, 131072>>>(cur, Wl[l], bl[l], nxt, (l == 4) ? 125 : 128, world);
        float* t = nxt; nxt = (float*)cur; cur = t;
    }
    dim3 g9(NPTS / 128, 2);
    k_last<<<g9, 512, 135168>>>(cur, Wl[9], bl[9], out);
}

// round 8
// speedup vs baseline: 6.3384x; 1.3745x over previous
#include <cuda_runtime.h>
#include <cuda_bf16.h>
#include <math.h>
#include <stdint.h>

#define NPTS 65536
#define Wdim 176
#define Ddim 132
#define LATD 128
#define OUTD 257
#define GB 8192

__device__ float g_bias[NPTS * LATD];
__device__ float g_partial[GB];
__device__ float g_scale;
// pre-split, pre-swizzled weights: [8 mid layers | last chunk0 | last chunk1]
__device__ uint32_t g_wh[82432];
__device__ uint32_t g_wl[82432];

// ---------------- helpers ----------------
__device__ __forceinline__ float sp100(float x) {
    return (x > 0.2f) ? x : (log1pf(expf(x * 100.0f)) * 0.01f);
}
__device__ __forceinline__ uint32_t smem_u32(const void* p) {
    uint32_t a;
    asm("{ .reg .u64 t; cvta.to.shared.u64 t, %1; cvt.u32.u64 %0, t; }" : "=r"(a) : "l"(p));
    return a;
}
__device__ __forceinline__ uint32_t swz(int r, int cp) {  // cp = even col idx, 256B rows
    const int kc = cp >> 3;
    return (uint32_t)(r * 256 + (((kc ^ (r & 7)) << 4) | ((cp * 2) & 15)));
}
__device__ __forceinline__ void split2(float a, float b, uint32_t& hi, uint32_t& lo) {
    __nv_bfloat16 ah = __float2bfloat16_rn(a), bh = __float2bfloat16_rn(b);
    __nv_bfloat16 al = __float2bfloat16_rn(a - __bfloat162float(ah));
    __nv_bfloat16 bl = __float2bfloat16_rn(b - __bfloat162float(bh));
    hi = (uint32_t)__bfloat16_as_ushort(ah) | ((uint32_t)__bfloat16_as_ushort(bh) << 16);
    lo = (uint32_t)__bfloat16_as_ushort(al) | ((uint32_t)__bfloat16_as_ushort(bl) << 16);
}
#define LDSM_X4(r, a) asm volatile( \
    "ldmatrix.sync.aligned.m8n8.x4.shared.b16 {%0,%1,%2,%3}, [%4];" \
    : "=r"((r)[0]), "=r"((r)[1]), "=r"((r)[2]), "=r"((r)[3]) : "r"(a))
#define LDSM_X2(r0, r1, a) asm volatile( \
    "ldmatrix.sync.aligned.m8n8.x2.shared.b16 {%0,%1}, [%2];" \
    : "=r"(r0), "=r"(r1) : "r"(a))
#define MMA(c, a, b0, b1) asm volatile( \
    "mma.sync.aligned.m16n8k16.row.col.f32.bf16.bf16.f32 " \
    "{%0,%1,%2,%3}, {%4,%5,%6,%7}, {%8,%9}, {%0,%1,%2,%3};" \
    : "+f"((c)[0]), "+f"((c)[1]), "+f"((c)[2]), "+f"((c)[3]) \
    : "r"((a)[0]), "r"((a)[1]), "r"((a)[2]), "r"((a)[3]), "r"(b0), "r"(b1))
#define CPA(dst, src) asm volatile("cp.async.cg.shared.global [%0], [%1], 16;" \
    :: "r"(dst), "l"(src) : "memory")
#define CPA_COMMIT() asm volatile("cp.async.commit_group;" ::: "memory")
#define CPA_WAIT1() asm volatile("cp.async.wait_group 1;" ::: "memory")
#define CPA_WAIT0() asm volatile("cp.async.wait_group 0;" ::: "memory")

// ============ gather: volume mix + Wq projection (Wq^T in smem) ============
__global__ void __launch_bounds__(256) k_gather(
    const float* __restrict__ pixel, const float* __restrict__ vol,
    const float* __restrict__ Wq, const float* __restrict__ bq)
{
    __shared__ float sWqT[32 * 129];
    __shared__ float sred[8];
    const int tid = threadIdx.x;
    for (int i = tid; i < 4096; i += 256) sWqT[(i & 31) * 129 + (i >> 5)] = Wq[i];
    __syncthreads();

    const int warp_g = (blockIdx.x * 256 + tid) >> 5;
    const int lane = tid & 31;
    const float qx = pixel[warp_g * 3 + 0] + 24.0f;
    const float qy = pixel[warp_g * 3 + 1] + 24.0f;
    const float qz = ((pixel[warp_g * 3 + 2] - 425.0f) / 480.0f) * 128.0f;
    const int bx = (int)floorf(qx), by = (int)floorf(qy), bz = (int)floorf(qz);

    float acc = 0.0f;
#pragma unroll 8
    for (int k = 0; k < 64; k++) {
        const int ix = bx + (k >> 4) - 1;
        const int iy = by + ((k >> 2) & 3) - 1;
        const int iz = bz + (k & 3) - 1;
        const float sim = (float)ix * qx + (float)iy * qy + (float)iz * qz;
        acc += sim * __ldg(vol + (((ix * Wdim) + iy) * Ddim + iz) * 32 + lane);
    }
    float tot = acc;
#pragma unroll
    for (int o = 16; o; o >>= 1) tot += __shfl_xor_sync(0xffffffffu, tot, o);
    const float feat = acc / tot;

    float r0 = bq[lane], r1 = bq[lane + 32], r2 = bq[lane + 64], r3 = bq[lane + 96];
#pragma unroll 8
    for (int f = 0; f < 32; f++) {
        const float xf = __shfl_sync(0xffffffffu, feat, f);
        const float* wr = sWqT + f * 129 + lane;
        r0 += wr[0] * xf; r1 += wr[32] * xf; r2 += wr[64] * xf; r3 += wr[96] * xf;
    }
    float* bp = g_bias + (size_t)warp_g * LATD;
    bp[lane] = r0; bp[lane + 32] = r1; bp[lane + 64] = r2; bp[lane + 96] = r3;

    float s = fabsf(r0) + fabsf(r1) + fabsf(r2) + fabsf(r3);
#pragma unroll
    for (int o = 16; o; o >>= 1) s += __shfl_xor_sync(0xffffffffu, s, o);
    if (lane == 0) sred[tid >> 5] = s;
    __syncthreads();
    if (tid == 0) {
        float t = 0.0f;
        for (int i = 0; i < 8; i++) t += sred[i];
        g_partial[blockIdx.x] = t;
    }
}

__global__ void k_reduce() {
    __shared__ float sm[256];
    float s = 0.0f;
    for (int i = threadIdx.x; i < GB; i += 256) s += g_partial[i];
    sm[threadIdx.x] = s;
    __syncthreads();
    for (int o = 128; o; o >>= 1) {
        if (threadIdx.x < o) sm[threadIdx.x] += sm[threadIdx.x + o];
        __syncthreads();
    }
    if (threadIdx.x == 0) g_scale = ((float)NPTS * (float)LATD) / sm[0];
}

// ============ weight prep: split + swizzle once ============
struct PW8 { const float* p[8]; };

__global__ void __launch_bounds__(256) k_prep_mid(PW8 wp) {
    const int id = blockIdx.x * 256 + threadIdx.x;     // 65536
    const int l = id >> 13, rem = id & 8191;
    const int r = rem >> 6, cp = (rem & 63) * 2;
    const int nvalid = (l == 3) ? 125 : 128;
    float2 wv = make_float2(0.f, 0.f);
    if (r < nvalid) wv = *(const float2*)(wp.p[l] + r * 128 + cp);
    uint32_t hi, lo;
    split2(wv.x, wv.y, hi, lo);
    const uint32_t o = l * 8192 + (swz(r, cp) >> 2);
    g_wh[o] = hi; g_wl[o] = lo;
}

__global__ void __launch_bounds__(256) k_prep_last(const float* __restrict__ W9) {
    const int id = blockIdx.x * 256 + threadIdx.x;     // 16896
    int r, cp, n, base;
    if (id < 8192) { r = id >> 6; cp = (id & 63) * 2; n = r; base = 65536; }
    else { const int rem = id - 8192; r = rem >> 6; cp = (rem & 63) * 2; n = 128 + r; base = 73728; }
    float2 wv = make_float2(0.f, 0.f);
    if (n < OUTD) wv = *(const float2*)(W9 + (size_t)n * 128 + cp);
    uint32_t hi, lo;
    split2(wv.x, wv.y, hi, lo);
    const uint32_t o = base + (swz(r, cp) >> 2);
    g_wh[o] = hi; g_wl[o] = lo;
}

// ============ fused persistent MLP ============
// smem: XH 0 | XL 32768 | Wbuf1 {H 65536, L 100352} | Wbuf0 {H 135168, L 169984}
#define WBH(p) (65536u + ((p) ? 0u : 69632u))
#define SMEM_FUSED 204800

struct FParams {
    const float* world;
    const float* W0;
    const float* b[10];
    float* out;
};

__device__ __forceinline__ void prefetch_w(uint32_t sb, int s, int tid) {
    const uint32_t dh = sb + WBH(s & 1), dl = dh + 34816;
    int off, bytes;
    if (s <= 8)      { off = (s - 1) * 8192; bytes = 32768; }
    else if (s == 9) { off = 65536;          bytes = 32768; }
    else             { off = 73728;          bytes = 34816; }
    const uint8_t* gh = (const uint8_t*)(g_wh + off);
    const uint8_t* gl = (const uint8_t*)(g_wl + off);
    for (int i = tid * 16; i < bytes; i += 512 * 16) {
        CPA(dh + i, gh + i);
        CPA(dl + i, gl + i);
    }
}

__device__ __forceinline__ void mma_phase(
    uint32_t sb, uint32_t wbh, uint32_t wbl, int T, int mb,
    float (*acc)[4], int hbase, bool extra)
{
    const int t7 = T & 7;
    const int arow = mb + t7 + ((T >> 3) & 1) * 8;
    const int akoff = (T >> 4) & 1;
    const int khalf = (T >> 3) & 1;
    const int nsel8 = ((T >> 4) & 1) * 8;
#pragma unroll
    for (int ks = 0; ks < 8; ks++) {
        uint32_t ah[4], al[4];
        const uint32_t ao = (uint32_t)(arow * 256 + (((2 * ks + akoff) ^ (arow & 7)) << 4));
        LDSM_X4(ah, sb + ao);
        LDSM_X4(al, sb + 32768 + ao);
        const uint32_t kx = (uint32_t)(((2 * ks + khalf) ^ t7) << 4);
        const uint32_t rowb = (uint32_t)((hbase + nsel8 + t7) * 256) + kx;
#pragma unroll
        for (int nb = 0; nb < 8; nb += 2) {
            uint32_t bh[4], bl4[4];
            const uint32_t bo = rowb + (uint32_t)(nb * 2048);
            LDSM_X4(bh, wbh + bo);
            LDSM_X4(bl4, wbl + bo);
            MMA(acc[nb], ah, bh[0], bh[1]);
            MMA(acc[nb], ah, bl4[0], bl4[1]);
            MMA(acc[nb], al, bh[0], bh[1]);
            MMA(acc[nb + 1], ah, bh[2], bh[3]);
            MMA(acc[nb + 1], ah, bl4[2], bl4[3]);
            MMA(acc[nb + 1], al, bh[2], bh[3]);
        }
        if (extra) {
            const uint32_t bo = (uint32_t)((hbase + 64 + t7) * 256) + kx;
            uint32_t b0, b1, c0, c1;
            LDSM_X2(b0, b1, wbh + bo);
            LDSM_X2(c0, c1, wbl + bo);
            MMA(acc[8], ah, b0, b1);
            MMA(acc[8], ah, c0, c1);
            MMA(acc[8], al, b0, b1);
        }
    }
}

__global__ void __launch_bounds__(512, 1) k_fused(FParams p) {
    extern __shared__ uint8_t sm[];
    const int tid = threadIdx.x, w = tid >> 5, T = tid & 31;
    const int m0 = blockIdx.x * 128;
    const uint32_t sb = smem_u32(sm);

    prefetch_w(sb, 1, tid);
    CPA_COMMIT();

    // layer 0: 3->128, * bias * scale, softplus -> X tiles
    {
        const float sc = g_scale;
        const float* W0 = p.W0;
        const float* b0 = p.b[0];
        for (int i = tid; i < 8192; i += 512) {
            const int m = i >> 6, cp = (i & 63) * 2;
            const float* wr = p.world + (size_t)(m0 + m) * 3;
            const float x0 = wr[0], x1 = wr[1], x2 = wr[2];
            float h0 = b0[cp] + W0[cp * 3] * x0 + W0[cp * 3 + 1] * x1 + W0[cp * 3 + 2] * x2;
            float h1 = b0[cp + 1] + W0[cp * 3 + 3] * x0 + W0[cp * 3 + 4] * x1 + W0[cp * 3 + 5] * x2;
            h0 *= g_bias[(size_t)(m0 + m) * LATD + cp] * sc;
            h1 *= g_bias[(size_t)(m0 + m) * LATD + cp + 1] * sc;
            uint32_t hi, lo;
            split2(sp100(h0), sp100(h1), hi, lo);
            const uint32_t o = swz(m, cp);
            *(uint32_t*)(sm + o) = hi;
            *(uint32_t*)(sm + 32768 + o) = lo;
        }
    }

    const int mb = (w & 7) * 16, nh = w >> 3;
    const int r1l = mb + (T >> 2), r2l = r1l + 8;
    float acc[9][4];

    for (int s = 1; s <= 10; s++) {
        if (s < 10) { prefetch_w(sb, s + 1, tid); CPA_COMMIT(); CPA_WAIT1(); }
        else CPA_WAIT0();
        __syncthreads();
        const uint32_t wbh = sb + WBH(s & 1), wbl = wbh + 34816;

        if (s <= 9) {
#pragma unroll
            for (int i = 0; i < 8; i++)
#pragma unroll
                for (int j = 0; j < 4; j++) acc[i][j] = 0.f;
            mma_phase(sb, wbh, wbl, T, mb, acc, nh * 64, false);

            if (s <= 8) {
                __syncthreads();
                const float* bs = p.b[s];
                const bool skl = (s == 4);
#pragma unroll
                for (int nb = 0; nb < 8; nb++) {
                    const int n = nh * 64 + nb * 8 + (T & 3) * 2;
                    float y0 = acc[nb][0] + bs[n], y1 = acc[nb][1] + bs[n + 1];
                    float y2 = acc[nb][2] + bs[n], y3 = acc[nb][3] + bs[n + 1];
                    if (skl && n >= 125) {
                        y0 = p.world[(size_t)(m0 + r1l) * 3 + (n - 125)];
                        y2 = p.world[(size_t)(m0 + r2l) * 3 + (n - 125)];
                    }
                    if (skl && n + 1 >= 125) {
                        y1 = p.world[(size_t)(m0 + r1l) * 3 + (n - 124)];
                        y3 = p.world[(size_t)(m0 + r2l) * 3 + (n - 124)];
                    }
                    uint32_t hi, lo;
                    split2(sp100(y0), sp100(y1), hi, lo);
                    uint32_t o = swz(r1l, n);
                    *(uint32_t*)(sm + o) = hi;
                    *(uint32_t*)(sm + 32768 + o) = lo;
                    split2(sp100(y2), sp100(y3), hi, lo);
                    o = swz(r2l, n);
                    *(uint32_t*)(sm + o) = hi;
                    *(uint32_t*)(sm + 32768 + o) = lo;
                }
                __syncthreads();
            } else {
                const float* b9 = p.b[9];
                float* o1 = p.out + (size_t)(m0 + r1l) * OUTD;
                float* o2 = p.out + (size_t)(m0 + r2l) * OUTD;
#pragma unroll
                for (int nb = 0; nb < 8; nb++) {
                    const int n = nh * 64 + nb * 8 + (T & 3) * 2;
                    o1[n] = acc[nb][0] + b9[n];
                    o1[n + 1] = acc[nb][1] + b9[n + 1];
                    o2[n] = acc[nb][2] + b9[n];
                    o2[n + 1] = acc[nb][3] + b9[n + 1];
                }
            }
        } else {
            const int nbcnt = nh ? 8 : 9;
            const int hbase = nh ? 72 : 0;
#pragma unroll
            for (int i = 0; i < 9; i++)
#pragma unroll
                for (int j = 0; j < 4; j++) acc[i][j] = 0.f;
            mma_phase(sb, wbh, wbl, T, mb, acc, hbase, nh == 0);

            const float* b9 = p.b[9];
            float* o1 = p.out + (size_t)(m0 + r1l) * OUTD;
            float* o2 = p.out + (size_t)(m0 + r2l) * OUTD;
            for (int nb = 0; nb < nbcnt; nb++) {
                const int n = 128 + hbase + nb * 8 + (T & 3) * 2;
                if (n < OUTD) { o1[n] = acc[nb][0] + b9[n]; o2[n] = acc[nb][2] + b9[n]; }
                if (n + 1 < OUTD) { o1[n + 1] = acc[nb][1] + b9[n + 1]; o2[n + 1] = acc[nb][3] + b9[n + 1]; }
            }
        }
    }
}

// ======================================================================
extern "C" void kernel_launch(void* const* d_in, const int* in_sizes, int n_in,
                              void* d_out, int out_size)
{
    const float* world = (const float*)d_in[0];
    const float* pixel = (const float*)d_in[1];
    const float* vol   = (const float*)d_in[2];
    const float* Wq    = (const float*)d_in[3];
    const float* bq    = (const float*)d_in[4];
    const float* Wl[10];
    const float* bl[10];
    for (int l = 0; l < 10; l++) {
        Wl[l] = (const float*)d_in[5 + 2 * l];
        bl[l] = (const float*)d_in[6 + 2 * l];
    }

    cudaFuncSetAttribute(k_fused, cudaFuncAttributeMaxDynamicSharedMemorySize, SMEM_FUSED);

    k_gather<<<GB, 256>>>(pixel, vol, Wq, bq);
    k_reduce<<<1, 256>>>();

    PW8 wp;
    for (int l = 0; l < 8; l++) wp.p[l] = Wl[l + 1];
    k_prep_mid<<<256, 256>>>(wp);
    k_prep_last<<<66, 256>>>(Wl[9]);

    FParams fp;
    fp.world = world;
    fp.W0 = Wl[0];
    for (int l = 0; l < 10; l++) fp.b[l] = bl[l];
    fp.out = (float*)d_out;
    k_fused<<<NPTS / 128, 512, SMEM_FUSED>>>(fp);
}